// round 2
// baseline (speedup 1.0000x reference)
#include <cuda_runtime.h>
#include <cstdint>

// Model_25855703122577: inputs [8192,784,1] f32, W_ih[30,1], W_hh[30,30],
// b_mod[30], W_lin[10,30], b_lin[10] -> out [8192,10] f32
#define RB   8192
#define RT   784
#define RH   30
#define RC   10
#define GRP  8          // threads per batch element (row-slices)
#define RPT  4          // hidden rows per thread (8*4=32 >= 30)
#define KP   15         // k-pairs (30 = 15*2 exact)
#define BPT  2          // batch elements per thread (weights amortized)
#define TPB  32         // one warp per block
#define SLOTS 8         // batch slots per block: 4 groups * 2
#define HSTR 36         // floats per h slot (144B: 16B-aligned, 4-bank group shift)

typedef unsigned long long u64;

__device__ __forceinline__ u64 fmul2(u64 a, u64 b) {
    u64 d; asm("mul.rn.f32x2 %0, %1, %2;" : "=l"(d) : "l"(a), "l"(b)); return d;
}
__device__ __forceinline__ u64 ffma2(u64 a, u64 b, u64 c) {
    u64 d; asm("fma.rn.f32x2 %0, %1, %2, %3;" : "=l"(d) : "l"(a), "l"(b), "l"(c)); return d;
}
__device__ __forceinline__ void unpack2(u64 v, float& lo, float& hi) {
    asm("mov.b64 {%0, %1}, %2;" : "=f"(lo), "=f"(hi) : "l"(v));
}

// modReLU epilogue for one z value
__device__ __forceinline__ float modrelu(float z, float b) {
    float m = fmaxf(fabsf(z) + b, 0.0f);
    float s = copysignf(m, z);
    return (z == 0.0f) ? 0.0f : s;
}

// One recurrence step for 2 batch elements (8 interleaved fma chains).
__device__ __forceinline__ void rnn_step2(
    float xa, float xb,
    const u64 (&w)[RPT][KP],
    const float (&wih)[RPT],
    const float (&bm)[RPT],
    const float* __restrict__ hsrcA, const float* __restrict__ hsrcB,
    float* __restrict__ hdstA, float* __restrict__ hdstB)
{
    // h as packed f32x2 via 128-bit shared loads (8 per batch, pairs 0..14 used)
    u64 pa[16], pb[16];
    const ulonglong2* ha = reinterpret_cast<const ulonglong2*>(hsrcA);
    const ulonglong2* hb = reinterpret_cast<const ulonglong2*>(hsrcB);
#pragma unroll
    for (int i = 0; i < 8; i++) {
        ulonglong2 va = ha[i]; pa[2*i] = va.x; pa[2*i+1] = va.y;
        ulonglong2 vb = hb[i]; pb[2*i] = vb.x; pb[2*i+1] = vb.y;
    }

    float hva[RPT], hvb[RPT];
#pragma unroll
    for (int r = 0; r < RPT; r++) {
        u64 aA = fmul2(w[r][0], pa[0]);
        u64 aB = fmul2(w[r][0], pb[0]);
#pragma unroll
        for (int p = 1; p < KP; p++) {
            aA = ffma2(w[r][p], pa[p], aA);
            aB = ffma2(w[r][p], pb[p], aB);
        }
        float loA, hiA, loB, hiB;
        unpack2(aA, loA, hiA);
        unpack2(aB, loB, hiB);
        float zA = fmaf(xa, wih[r], loA + hiA);
        float zB = fmaf(xb, wih[r], loB + hiB);
        hva[r] = modrelu(zA, bm[r]);
        hvb[r] = modrelu(zB, bm[r]);
    }
    *reinterpret_cast<float4*>(hdstA) = make_float4(hva[0], hva[1], hva[2], hva[3]);
    *reinterpret_cast<float4*>(hdstB) = make_float4(hvb[0], hvb[1], hvb[2], hvb[3]);
    __syncwarp();
}

extern "C" __global__ void __launch_bounds__(TPB)
rnn_modrelu_kernel(const float* __restrict__ inputs,  // [B, T]
                   const float* __restrict__ W_ih,    // [H]
                   const float* __restrict__ W_hh,    // [H, H]
                   const float* __restrict__ b_mod,   // [H]
                   const float* __restrict__ W_lin,   // [C, H]
                   const float* __restrict__ b_lin,   // [C]
                   float* __restrict__ out)           // [B, C]
{
    __shared__ float hbuf[2][SLOTS][HSTR];

    const int tid = threadIdx.x;           // 0..31
    const int sub = tid & (GRP - 1);       // 0..7 row-slice
    const int g   = tid >> 3;              // 0..3 group
    const int sA  = g;                     // slot for batch A
    const int sB  = g + 4;                 // slot for batch B
    const int bA  = blockIdx.x * SLOTS + sA;
    const int bB  = blockIdx.x * SLOTS + sB;

    // ---- register-resident weight slice (shared by both batches) ----
    u64 w[RPT][KP];
    float wih[RPT], bm[RPT];
#pragma unroll
    for (int r = 0; r < RPT; r++) {
        const int row = sub * RPT + r;
        if (row < RH) {
            const u64* wr = reinterpret_cast<const u64*>(W_hh + row * RH);
#pragma unroll
            for (int p = 0; p < KP; p++) w[r][p] = wr[p];
            wih[r] = W_ih[row];
            bm[r]  = b_mod[row];
        } else {
#pragma unroll
            for (int p = 0; p < KP; p++) w[r][p] = 0ULL;
            wih[r] = 0.0f;
            bm[r]  = 0.0f;
        }
    }

    // h0 = 0 (also zero the pad floats so LDS.128 pads are defined)
    *reinterpret_cast<float4*>(&hbuf[0][sA][sub * 4]) = make_float4(0, 0, 0, 0);
    *reinterpret_cast<float4*>(&hbuf[0][sB][sub * 4]) = make_float4(0, 0, 0, 0);
    if (sub < 2) {   // floats 32..35 unused; zero 30,31 region via slot pad
        hbuf[0][sA][32 + sub] = 0.0f;
        hbuf[0][sB][32 + sub] = 0.0f;
    }
    __syncwarp();

    const float* xrA = inputs + (size_t)bA * RT;
    const float* xrB = inputs + (size_t)bB * RT;

#pragma unroll 1
    for (int t0 = 0; t0 < RT; t0 += 4) {
        const float4 x4a = *reinterpret_cast<const float4*>(xrA + t0);
        const float4 x4b = *reinterpret_cast<const float4*>(xrB + t0);
        rnn_step2(x4a.x, x4b.x, w, wih, bm,
                  &hbuf[0][sA][0], &hbuf[0][sB][0],
                  &hbuf[1][sA][sub * 4], &hbuf[1][sB][sub * 4]);
        rnn_step2(x4a.y, x4b.y, w, wih, bm,
                  &hbuf[1][sA][0], &hbuf[1][sB][0],
                  &hbuf[0][sA][sub * 4], &hbuf[0][sB][sub * 4]);
        rnn_step2(x4a.z, x4b.z, w, wih, bm,
                  &hbuf[0][sA][0], &hbuf[0][sB][0],
                  &hbuf[1][sA][sub * 4], &hbuf[1][sB][sub * 4]);
        rnn_step2(x4a.w, x4b.w, w, wih, bm,
                  &hbuf[1][sA][0], &hbuf[1][sB][0],
                  &hbuf[0][sA][sub * 4], &hbuf[0][sB][sub * 4]);
    }
    // T=784 even -> final h in buffer 0

    // ---- fused classifier: out[b][c] = h . W_lin[c] + b_lin[c] ----
#pragma unroll 1
    for (int pass = 0; pass < BPT; pass++) {
        const int slot = (pass == 0) ? sA : sB;
        const int b    = (pass == 0) ? bA : bB;
        const float* hf = &hbuf[0][slot][0];
#pragma unroll 1
        for (int c = sub; c < RC; c += GRP) {
            float acc = b_lin[c];
            const float* wl = W_lin + c * RH;
#pragma unroll
            for (int k = 0; k < RH; k++) acc = fmaf(hf[k], wl[k], acc);
            out[(size_t)b * RC + c] = acc;
        }
    }
}

extern "C" void kernel_launch(void* const* d_in, const int* in_sizes, int n_in,
                              void* d_out, int out_size) {
    const float* inputs = (const float*)d_in[0];
    const float* W_ih   = (const float*)d_in[1];
    const float* W_hh   = (const float*)d_in[2];
    const float* b_mod  = (const float*)d_in[3];
    const float* W_lin  = (const float*)d_in[4];
    const float* b_lin  = (const float*)d_in[5];
    float* out = (float*)d_out;

    dim3 grid(RB / SLOTS);   // 1024 one-warp blocks -> single wave (<=8 warps/SM)
    dim3 block(TPB);
    rnn_modrelu_kernel<<<grid, block>>>(inputs, W_ih, W_hh, b_mod,
                                        W_lin, b_lin, out);
}